// round 8
// baseline (speedup 1.0000x reference)
#include <cuda_runtime.h>
#include <cuda_fp16.h>
#include <stdint.h>

// ---------------------------------------------------------------------------
// Sparse gather-MLP (B=32768, 8 layers, W=256, K=16 random gathers/unit).
//
// Per-block batch tile of R=60 rows entirely in shared memory, feature-major
// fp16 [feat][60 rows]. Gather index is uniform across the warp ->
// conflict-free LDS.32 of half2 (2 rows/lane, lanes 0..29 active).
// Pair table {byte_off, half2(w)} prepacked in gmem, uniform LDG.128.
//
// R7: half-unit software pipeline on the pair table (prefetch next 8 pairs
// while computing current 8) to hide L2 latency; bias folded into
// accumulator init; 2 pad launches so ncu -s 5 -c 1 lands on ffn_main.
// ---------------------------------------------------------------------------

#define NLAYER 8
#define WIDTH  256
#define KK     16
#define NIN    128
#define BB     32768
#define RROWS  60
#define ROW_BYTES (RROWS * 2)                       // 120 bytes per feature row
#define TOTAL_FEAT (NIN + (NLAYER - 1) * WIDTH)     // 1920 stored features
#define SMEM_BYTES (TOTAL_FEAT * ROW_BYTES + 256)   // + pad for lane 30/31 overread
#define NPAIR (NLAYER * WIDTH * KK)
#define NTHREADS 1024
#define UNITS_PER_WARP (WIDTH / (NTHREADS / 32))    // 8

struct Pair { uint32_t off; uint32_t w2; };         // byte offset, half2 weight

__device__ Pair    g_pairs[NPAIR];                  // 256 KB prepacked table
__device__ __half2 g_bias2[NLAYER * WIDTH];         // bias as half2 (broadcast)
__device__ float   g_out_t[(size_t)WIDTH * BB];     // transposed output scratch

// --------------------------- prepack -------------------------------------
__global__ void prepack_kernel(const float* __restrict__ w,
                               const int* __restrict__ e,
                               const float* __restrict__ b) {
    int i = blockIdx.x * blockDim.x + threadIdx.x;
    if (i < NPAIR) {
        __half2 h = __float2half2_rn(w[i]);
        Pair p;
        p.off = (uint32_t)e[i] * (uint32_t)ROW_BYTES;
        p.w2  = *reinterpret_cast<uint32_t*>(&h);
        g_pairs[i] = p;
    }
    if (i < NLAYER * WIDTH) g_bias2[i] = __float2half2_rn(b[i]);
}

// pad launches: shift ncu's (-s 5 -c 1) profiled launch onto ffn_main
__global__ void pad_kernel() {}

__device__ __forceinline__ __half2 h2bits(uint32_t u) {
    return *reinterpret_cast<__half2*>(&u);
}

__device__ __forceinline__ __half2 h2_tanh(__half2 x) {
    uint32_t xi = *reinterpret_cast<uint32_t*>(&x), yo;
    asm("tanh.approx.f16x2 %0, %1;" : "=r"(yo) : "r"(xi));
    return *reinterpret_cast<__half2*>(&yo);
}

__device__ __forceinline__ float sigmoid_ref(float x) {
    return __fdividef(1.f, 1.f + __expf(-x));
}

// 8 gathers (one half-unit) from 4 packed uint4 pairs
#define FMA8(c0, c1, c2, c3)                                              \
    do {                                                                  \
        a0 = __hfma2(*(const __half2*)(smlb + (c0).x), h2bits((c0).y), a0); \
        a1 = __hfma2(*(const __half2*)(smlb + (c0).z), h2bits((c0).w), a1); \
        a2 = __hfma2(*(const __half2*)(smlb + (c1).x), h2bits((c1).y), a2); \
        a3 = __hfma2(*(const __half2*)(smlb + (c1).z), h2bits((c1).w), a3); \
        a0 = __hfma2(*(const __half2*)(smlb + (c2).x), h2bits((c2).y), a0); \
        a1 = __hfma2(*(const __half2*)(smlb + (c2).z), h2bits((c2).w), a1); \
        a2 = __hfma2(*(const __half2*)(smlb + (c3).x), h2bits((c3).y), a2); \
        a3 = __hfma2(*(const __half2*)(smlb + (c3).z), h2bits((c3).w), a3); \
    } while (0)

// --------------------------- one layer ------------------------------------
template <bool LAST>
__device__ __forceinline__ void do_layer(char* sm, char* smlb, int l, int warp,
                                         int lane, int row0, bool active) {
    const int width = NIN + l * WIDTH;
    const int w0    = warp * UNITS_PER_WARP;     // 32 warps x 8 units = 256
    const __half2* bl   = g_bias2 + l * WIDTH + w0;
    const uint4*   base = reinterpret_cast<const uint4*>(
                              g_pairs + (size_t)(l * WIDTH + w0) * KK); // 8 uint4/unit
    const int      lb   = lane * 4;
    const __half2  h05  = __float2half2_rn(0.5f);

    // prime pipeline: half A of unit 0
    uint4 c0 = __ldg(base + 0), c1 = __ldg(base + 1);
    uint4 c2 = __ldg(base + 2), c3 = __ldg(base + 3);

#pragma unroll 1
    for (int u = 0; u < UNITS_PER_WARP; ++u) {
        const uint4* pu = base + u * 8;
        __half2 a0 = __ldg(bl + u);                   // bias-initialized acc
        __half2 a1 = __float2half2_rn(0.f), a2 = a1, a3 = a1;

        // prefetch half B of unit u, then consume half A (in c*)
        uint4 n0 = __ldg(pu + 4), n1 = __ldg(pu + 5);
        uint4 n2 = __ldg(pu + 6), n3 = __ldg(pu + 7);
        FMA8(c0, c1, c2, c3);

        // prefetch half A of unit u+1 (clamped), then consume half B (in n*)
        const uint4* pv = (u + 1 < UNITS_PER_WARP) ? pu + 8 : base;
        c0 = __ldg(pv + 0); c1 = __ldg(pv + 1);
        c2 = __ldg(pv + 2); c3 = __ldg(pv + 3);
        FMA8(n0, n1, n2, n3);

        // combine + activation
        __half2 s = __hadd2(__hadd2(a0, a1), __hadd2(a2, a3));
        if (!LAST) {
            // sigmoid(x) = 0.5 + 0.5*tanh(x/2), all fp16x2
            __half2 t = h2_tanh(__hmul2(s, h05));
            __half2 o = __hfma2(t, h05, h05);
            if (active)
                *(__half2*)(sm + (width + w0 + u) * ROW_BYTES + lb) = o;
        } else {
            float2 f = __half22float2(s);
            float s0 = sigmoid_ref(f.x), s1 = sigmoid_ref(f.y);
            if (active) {
                int r = row0 + 2 * lane;
                if (r < BB) {
                    *reinterpret_cast<float2*>(&g_out_t[(size_t)(w0 + u) * BB + r]) =
                        make_float2(s0, s1);
                }
            }
        }
    }
}

// --------------------------- main kernel -----------------------------------
__global__ void __launch_bounds__(NTHREADS, 1)
ffn_main(const float* __restrict__ inp) {
    extern __shared__ char sm[];
    const int tid  = threadIdx.x;
    const int lane = tid & 31;
    const int warp = tid >> 5;
    const int row0 = blockIdx.x * RROWS;

    // stage input tile [60 rows x 128 feats] transposed into smem as fp16
    for (int idx = tid; idx < RROWS * NIN; idx += NTHREADS) {
        int r = idx >> 7;          // 0..59
        int c = idx & 127;         // coalesced gmem read over c
        float v = 0.f;
        int gr = row0 + r;
        if (gr < BB) v = inp[gr * NIN + c];
        *reinterpret_cast<__half*>(sm + c * ROW_BYTES + r * 2) = __float2half_rn(v);
    }
    __syncthreads();

    char* smlb = sm + lane * 4;                // per-lane gather base
    const bool active = lane < (RROWS / 2);    // 30 row-pairs per warp

#pragma unroll 1
    for (int l = 0; l < NLAYER - 1; ++l) {
        do_layer<false>(sm, smlb, l, warp, lane, row0, active);
        __syncthreads();   // layer-l outputs visible before layer-(l+1) gathers
    }
    do_layer<true>(sm, smlb, NLAYER - 1, warp, lane, row0, active);
}

// --------------------------- output transpose ------------------------------
__global__ void transpose_kernel(float* __restrict__ out) {
    __shared__ float t[32][33];
    int rb = blockIdx.x * 32;    // row tile
    int cb = blockIdx.y * 32;    // feature tile
    int x = threadIdx.x, y = threadIdx.y;   // 32 x 8
#pragma unroll
    for (int i = 0; i < 32; i += 8)
        t[y + i][x] = g_out_t[(size_t)(cb + y + i) * BB + rb + x];
    __syncthreads();
#pragma unroll
    for (int i = 0; i < 32; i += 8)
        out[(size_t)(rb + y + i) * WIDTH + cb + x] = t[x][y + i];
}

// --------------------------- launcher --------------------------------------
extern "C" void kernel_launch(void* const* d_in, const int* in_sizes, int n_in,
                              void* d_out, int out_size) {
    const float* inp     = (const float*)d_in[0];   // (32768, 128) f32
    const float* weights = (const float*)d_in[1];   // (8, 256, 16) f32
    const float* biases  = (const float*)d_in[2];   // (8, 256)     f32
    const int*   edge    = (const int*)  d_in[3];   // (8, 256, 16) i32
    float* out = (float*)d_out;                     // (32768, 256) f32

    cudaFuncSetAttribute(ffn_main, cudaFuncAttributeMaxDynamicSharedMemorySize,
                         SMEM_BYTES);

    prepack_kernel<<<(NPAIR + 255) / 256, 256>>>(weights, edge, biases);
    pad_kernel<<<1, 32>>>();   // alignment pads: put ffn_main at ncu launch #6
    pad_kernel<<<1, 32>>>();
    ffn_main<<<(BB + RROWS - 1) / RROWS, NTHREADS, SMEM_BYTES>>>(inp);
    transpose_kernel<<<dim3(BB / 32, WIDTH / 32), dim3(32, 8)>>>(out);
}

// round 9
// speedup vs baseline: 1.2556x; 1.2556x over previous
#include <cuda_runtime.h>
#include <cuda_fp16.h>
#include <stdint.h>

// ---------------------------------------------------------------------------
// Sparse gather-MLP (B=32768, 8 layers, W=256, K=16 random gathers/unit).
//
// Per-block batch tile of R=60 rows entirely in shared memory, feature-major
// fp16 [feat][60 rows]. Gather index is uniform across the warp ->
// conflict-free LDS.32 of half2 (2 rows/lane, lanes 0..29 active).
//
// R8: L1TEX was the binding pipe (77%) and uniform pair-table LDG.128s cost
// more LSU cycles than the gathers. Pairs now packed 4B each:
//   lo16 = (idx*120)>>3  (8-aligned smem byte offset, pre-shifted)
//   hi16 = fp16 weight   (consumed via HFMA2 .H1_H1 half-select)
// -> 4 LDG.128 per unit instead of 8. Unpack = AND + LEA per gather.
// ---------------------------------------------------------------------------

#define NLAYER 8
#define WIDTH  256
#define KK     16
#define NIN    128
#define BB     32768
#define RROWS  60
#define ROW_BYTES (RROWS * 2)                       // 120 bytes per feature row
#define TOTAL_FEAT (NIN + (NLAYER - 1) * WIDTH)     // 1920 stored features
#define SMEM_BYTES (TOTAL_FEAT * ROW_BYTES + 256)   // + pad for lane 30/31 overread
#define NPAIR (NLAYER * WIDTH * KK)
#define NTHREADS 1024
#define UNITS_PER_WARP (WIDTH / (NTHREADS / 32))    // 8

__device__ uint32_t g_pack[NPAIR];                  // 128 KB packed pair table
__device__ __half2  g_bias2[NLAYER * WIDTH];        // bias as half2 (broadcast)
__device__ float    g_out_t[(size_t)WIDTH * BB];    // transposed output scratch

// --------------------------- prepack -------------------------------------
__global__ void prepack_kernel(const float* __restrict__ w,
                               const int* __restrict__ e,
                               const float* __restrict__ b) {
    int i = blockIdx.x * blockDim.x + threadIdx.x;
    if (i < NPAIR) {
        __half h = __float2half_rn(w[i]);
        uint32_t hb = (uint32_t)*reinterpret_cast<unsigned short*>(&h);
        uint32_t off3 = ((uint32_t)e[i] * (uint32_t)ROW_BYTES) >> 3;  // < 2^15
        g_pack[i] = off3 | (hb << 16);
    }
    if (i < NLAYER * WIDTH) g_bias2[i] = __float2half2_rn(b[i]);
}

// pad launches: shift ncu's (-s 5 -c 1) profiled launch onto ffn_main
__global__ void pad_kernel() {}

__device__ __forceinline__ __half2 h2_tanh(__half2 x) {
    uint32_t xi = *reinterpret_cast<uint32_t*>(&x), yo;
    asm("tanh.approx.f16x2 %0, %1;" : "=r"(yo) : "r"(xi));
    return *reinterpret_cast<__half2*>(&yo);
}

__device__ __forceinline__ float sigmoid_ref(float x) {
    return __fdividef(1.f, 1.f + __expf(-x));
}

// one gather from one packed word; weight = hi half broadcast (.H1_H1 fold)
#define G(acc, word)                                                        \
    do {                                                                    \
        const __half2* _v = (const __half2*)(smlb + (((word) & 0xFFFFu) << 3)); \
        __half2 _w = *reinterpret_cast<const __half2*>(&(word));            \
        (acc) = __hfma2(*_v, __high2half2(_w), (acc));                      \
    } while (0)

// 16 gathers from 4 packed uint4 (round-robin over 4 fp16 accumulators)
#define FMA16(c0, c1, c2, c3)                      \
    do {                                           \
        G(a0, (c0).x); G(a1, (c0).y); G(a2, (c0).z); G(a3, (c0).w); \
        G(a0, (c1).x); G(a1, (c1).y); G(a2, (c1).z); G(a3, (c1).w); \
        G(a0, (c2).x); G(a1, (c2).y); G(a2, (c2).z); G(a3, (c2).w); \
        G(a0, (c3).x); G(a1, (c3).y); G(a2, (c3).z); G(a3, (c3).w); \
    } while (0)

// --------------------------- one layer ------------------------------------
template <bool LAST>
__device__ __forceinline__ void do_layer(char* sm, char* smlb, int l, int warp,
                                         int lane, int row0, bool active) {
    const int width = NIN + l * WIDTH;
    const int w0    = warp * UNITS_PER_WARP;     // 32 warps x 8 units = 256
    const __half2* bl   = g_bias2 + l * WIDTH + w0;
    const uint4*   base = reinterpret_cast<const uint4*>(
                              g_pack + (size_t)(l * WIDTH + w0) * KK); // 4 uint4/unit
    const int      lb   = lane * 4;
    const __half2  h05  = __float2half2_rn(0.5f);

    // prime pipeline: unit 0's packed pairs
    uint4 c0 = __ldg(base + 0), c1 = __ldg(base + 1);
    uint4 c2 = __ldg(base + 2), c3 = __ldg(base + 3);

#pragma unroll 1
    for (int u = 0; u < UNITS_PER_WARP; ++u) {
        // prefetch next unit's pairs (clamped) before consuming current
        const uint4* pn = base + ((u + 1 < UNITS_PER_WARP) ? (u + 1) * 4 : 0);
        uint4 n0 = __ldg(pn + 0), n1 = __ldg(pn + 1);
        uint4 n2 = __ldg(pn + 2), n3 = __ldg(pn + 3);

        __half2 a0 = __ldg(bl + u);                   // bias-initialized acc
        __half2 a1 = __float2half2_rn(0.f), a2 = a1, a3 = a1;
        FMA16(c0, c1, c2, c3);

        // combine + activation
        __half2 s = __hadd2(__hadd2(a0, a1), __hadd2(a2, a3));
        if (!LAST) {
            // sigmoid(x) = 0.5 + 0.5*tanh(x/2), all fp16x2
            __half2 t = h2_tanh(__hmul2(s, h05));
            __half2 o = __hfma2(t, h05, h05);
            if (active)
                *(__half2*)(sm + (width + w0 + u) * ROW_BYTES + lb) = o;
        } else {
            float2 f = __half22float2(s);
            float s0 = sigmoid_ref(f.x), s1 = sigmoid_ref(f.y);
            if (active) {
                int r = row0 + 2 * lane;
                if (r < BB) {
                    *reinterpret_cast<float2*>(&g_out_t[(size_t)(w0 + u) * BB + r]) =
                        make_float2(s0, s1);
                }
            }
        }

        c0 = n0; c1 = n1; c2 = n2; c3 = n3;
    }
}

// --------------------------- main kernel -----------------------------------
__global__ void __launch_bounds__(NTHREADS, 1)
ffn_main(const float* __restrict__ inp) {
    extern __shared__ char sm[];
    const int tid  = threadIdx.x;
    const int lane = tid & 31;
    const int warp = tid >> 5;
    const int row0 = blockIdx.x * RROWS;

    // stage input tile [60 rows x 128 feats] transposed into smem as fp16
    for (int idx = tid; idx < RROWS * NIN; idx += NTHREADS) {
        int r = idx >> 7;          // 0..59
        int c = idx & 127;         // coalesced gmem read over c
        float v = 0.f;
        int gr = row0 + r;
        if (gr < BB) v = inp[gr * NIN + c];
        *reinterpret_cast<__half*>(sm + c * ROW_BYTES + r * 2) = __float2half_rn(v);
    }
    __syncthreads();

    char* smlb = sm + lane * 4;                // per-lane gather base
    const bool active = lane < (RROWS / 2);    // 30 row-pairs per warp

#pragma unroll 1
    for (int l = 0; l < NLAYER - 1; ++l) {
        do_layer<false>(sm, smlb, l, warp, lane, row0, active);
        __syncthreads();   // layer-l outputs visible before layer-(l+1) gathers
    }
    do_layer<true>(sm, smlb, NLAYER - 1, warp, lane, row0, active);
}

// --------------------------- output transpose ------------------------------
__global__ void transpose_kernel(float* __restrict__ out) {
    __shared__ float t[32][33];
    int rb = blockIdx.x * 32;    // row tile
    int cb = blockIdx.y * 32;    // feature tile
    int x = threadIdx.x, y = threadIdx.y;   // 32 x 8
#pragma unroll
    for (int i = 0; i < 32; i += 8)
        t[y + i][x] = g_out_t[(size_t)(cb + y + i) * BB + rb + x];
    __syncthreads();
#pragma unroll
    for (int i = 0; i < 32; i += 8)
        out[(size_t)(rb + y + i) * WIDTH + cb + x] = t[x][y + i];
}

// --------------------------- launcher --------------------------------------
extern "C" void kernel_launch(void* const* d_in, const int* in_sizes, int n_in,
                              void* d_out, int out_size) {
    const float* inp     = (const float*)d_in[0];   // (32768, 128) f32
    const float* weights = (const float*)d_in[1];   // (8, 256, 16) f32
    const float* biases  = (const float*)d_in[2];   // (8, 256)     f32
    const int*   edge    = (const int*)  d_in[3];   // (8, 256, 16) i32
    float* out = (float*)d_out;                     // (32768, 256) f32

    cudaFuncSetAttribute(ffn_main, cudaFuncAttributeMaxDynamicSharedMemorySize,
                         SMEM_BYTES);

    prepack_kernel<<<(NPAIR + 255) / 256, 256>>>(weights, edge, biases);
    pad_kernel<<<1, 32>>>();   // alignment pads: put ffn_main at ncu launch #6
    pad_kernel<<<1, 32>>>();
    ffn_main<<<(BB + RROWS - 1) / RROWS, NTHREADS, SMEM_BYTES>>>(inp);
    transpose_kernel<<<dim3(BB / 32, WIDTH / 32), dim3(32, 8)>>>(out);
}

// round 11
// speedup vs baseline: 1.2882x; 1.0259x over previous
#include <cuda_runtime.h>
#include <cuda_fp16.h>
#include <stdint.h>

// ---------------------------------------------------------------------------
// Sparse gather-MLP (B=32768, 8 layers, W=256, K=16 random gathers/unit).
//
// Per-block batch tile of R=60 rows entirely in shared memory, feature-major
// fp16 [feat][60 rows]. Gather index is uniform across the warp ->
// conflict-free LDS.32 of half2 (2 rows/lane, lanes 0..29 active).
// Pair table packed 4B/pair: lo16=(idx*120)>>3, hi16=fp16 weight
// (weight consumed via HFMA2 half-select broadcast).
//
// R10 = R9 resubmitted verbatim (previous bench died to container infra, not
// the kernel): software prefetch dropped (measured neutral for latency at
// 8 warps/SMSP; its clamp+register-rotation was pure issue overhead and
// pushed regs to the 64 cap); 4 accumulators -> 2 (a0 bias-initialized).
// L1tex + issue are co-binding; this trims issue.
// ---------------------------------------------------------------------------

#define NLAYER 8
#define WIDTH  256
#define KK     16
#define NIN    128
#define BB     32768
#define RROWS  60
#define ROW_BYTES (RROWS * 2)                       // 120 bytes per feature row
#define TOTAL_FEAT (NIN + (NLAYER - 1) * WIDTH)     // 1920 stored features
#define SMEM_BYTES (TOTAL_FEAT * ROW_BYTES + 256)   // + pad for lane 30/31 overread
#define NPAIR (NLAYER * WIDTH * KK)
#define NTHREADS 1024
#define UNITS_PER_WARP (WIDTH / (NTHREADS / 32))    // 8

__device__ __align__(256) uint32_t g_pack[NPAIR];   // 128 KB packed pair table
__device__ __half2  g_bias2[NLAYER * WIDTH];        // bias as half2 (broadcast)
__device__ float    g_out_t[(size_t)WIDTH * BB];    // transposed output scratch

// --------------------------- prepack -------------------------------------
__global__ void prepack_kernel(const float* __restrict__ w,
                               const int* __restrict__ e,
                               const float* __restrict__ b) {
    int i = blockIdx.x * blockDim.x + threadIdx.x;
    if (i < NPAIR) {
        __half h = __float2half_rn(w[i]);
        uint32_t hb = (uint32_t)*reinterpret_cast<unsigned short*>(&h);
        uint32_t off3 = ((uint32_t)e[i] * (uint32_t)ROW_BYTES) >> 3;  // < 2^15
        g_pack[i] = off3 | (hb << 16);
    }
    if (i < NLAYER * WIDTH) g_bias2[i] = __float2half2_rn(b[i]);
}

// pad launches: keep ncu's (-s 5 -c 1) profiled launch on ffn_main
__global__ void pad_kernel() {}

__device__ __forceinline__ __half2 h2_tanh(__half2 x) {
    uint32_t xi = *reinterpret_cast<uint32_t*>(&x), yo;
    asm("tanh.approx.f16x2 %0, %1;" : "=r"(yo) : "r"(xi));
    return *reinterpret_cast<__half2*>(&yo);
}

__device__ __forceinline__ float sigmoid_ref(float x) {
    return __fdividef(1.f, 1.f + __expf(-x));
}

// one gather from one packed word; weight = hi half broadcast
#define G(acc, word)                                                        \
    do {                                                                    \
        const __half2* _v = (const __half2*)(smlb + (((word) & 0xFFFFu) << 3)); \
        __half2 _w = *reinterpret_cast<const __half2*>(&(word));            \
        (acc) = __hfma2(*_v, __high2half2(_w), (acc));                      \
    } while (0)

// 16 gathers from 4 packed uint4 (alternating over 2 fp16 accumulators)
#define FMA16(c0, c1, c2, c3)                      \
    do {                                           \
        G(a0, (c0).x); G(a1, (c0).y); G(a0, (c0).z); G(a1, (c0).w); \
        G(a0, (c1).x); G(a1, (c1).y); G(a0, (c1).z); G(a1, (c1).w); \
        G(a0, (c2).x); G(a1, (c2).y); G(a0, (c2).z); G(a1, (c2).w); \
        G(a0, (c3).x); G(a1, (c3).y); G(a0, (c3).z); G(a1, (c3).w); \
    } while (0)

// --------------------------- one layer ------------------------------------
template <bool LAST>
__device__ __forceinline__ void do_layer(char* sm, char* smlb, int l, int warp,
                                         int lane, int row0, bool active) {
    const int width = NIN + l * WIDTH;
    const int w0    = warp * UNITS_PER_WARP;     // 32 warps x 8 units = 256
    const __half2* bl   = g_bias2 + l * WIDTH + w0;
    const uint4*   base = reinterpret_cast<const uint4*>(
                              g_pack + (size_t)(l * WIDTH + w0) * KK); // 4 uint4/unit
    const int      lb   = lane * 4;
    const __half2  h05  = __float2half2_rn(0.5f);

#pragma unroll 1
    for (int u = 0; u < UNITS_PER_WARP; ++u) {
        const uint4* pu = base + u * 4;
        uint4 c0 = __ldg(pu + 0), c1 = __ldg(pu + 1);
        uint4 c2 = __ldg(pu + 2), c3 = __ldg(pu + 3);

        __half2 a0 = __ldg(bl + u);                   // bias-initialized acc
        __half2 a1 = __float2half2_rn(0.f);
        FMA16(c0, c1, c2, c3);

        // combine + activation
        __half2 s = __hadd2(a0, a1);
        if (!LAST) {
            // sigmoid(x) = 0.5 + 0.5*tanh(x/2), all fp16x2
            __half2 t = h2_tanh(__hmul2(s, h05));
            __half2 o = __hfma2(t, h05, h05);
            if (active)
                *(__half2*)(sm + (width + w0 + u) * ROW_BYTES + lb) = o;
        } else {
            float2 f = __half22float2(s);
            float s0 = sigmoid_ref(f.x), s1 = sigmoid_ref(f.y);
            if (active) {
                int r = row0 + 2 * lane;
                if (r < BB) {
                    *reinterpret_cast<float2*>(&g_out_t[(size_t)(w0 + u) * BB + r]) =
                        make_float2(s0, s1);
                }
            }
        }
    }
}

// --------------------------- main kernel -----------------------------------
__global__ void __launch_bounds__(NTHREADS, 1)
ffn_main(const float* __restrict__ inp) {
    extern __shared__ char sm[];
    const int tid  = threadIdx.x;
    const int lane = tid & 31;
    const int warp = tid >> 5;
    const int row0 = blockIdx.x * RROWS;

    // stage input tile [60 rows x 128 feats] transposed into smem as fp16
    for (int idx = tid; idx < RROWS * NIN; idx += NTHREADS) {
        int r = idx >> 7;          // 0..59
        int c = idx & 127;         // coalesced gmem read over c
        float v = 0.f;
        int gr = row0 + r;
        if (gr < BB) v = inp[gr * NIN + c];
        *reinterpret_cast<__half*>(sm + c * ROW_BYTES + r * 2) = __float2half_rn(v);
    }
    __syncthreads();

    char* smlb = sm + lane * 4;                // per-lane gather base
    const bool active = lane < (RROWS / 2);    // 30 row-pairs per warp

#pragma unroll 1
    for (int l = 0; l < NLAYER - 1; ++l) {
        do_layer<false>(sm, smlb, l, warp, lane, row0, active);
        __syncthreads();   // layer-l outputs visible before layer-(l+1) gathers
    }
    do_layer<true>(sm, smlb, NLAYER - 1, warp, lane, row0, active);
}

// --------------------------- output transpose ------------------------------
__global__ void transpose_kernel(float* __restrict__ out) {
    __shared__ float t[32][33];
    int rb = blockIdx.x * 32;    // row tile
    int cb = blockIdx.y * 32;    // feature tile
    int x = threadIdx.x, y = threadIdx.y;   // 32 x 8
#pragma unroll
    for (int i = 0; i < 32; i += 8)
        t[y + i][x] = g_out_t[(size_t)(cb + y + i) * BB + rb + x];
    __syncthreads();
#pragma unroll
    for (int i = 0; i < 32; i += 8)
        out[(size_t)(rb + y + i) * WIDTH + cb + x] = t[x][y + i];
}

// --------------------------- launcher --------------------------------------
extern "C" void kernel_launch(void* const* d_in, const int* in_sizes, int n_in,
                              void* d_out, int out_size) {
    const float* inp     = (const float*)d_in[0];   // (32768, 128) f32
    const float* weights = (const float*)d_in[1];   // (8, 256, 16) f32
    const float* biases  = (const float*)d_in[2];   // (8, 256)     f32
    const int*   edge    = (const int*)  d_in[3];   // (8, 256, 16) i32
    float* out = (float*)d_out;                     // (32768, 256) f32

    cudaFuncSetAttribute(ffn_main, cudaFuncAttributeMaxDynamicSharedMemorySize,
                         SMEM_BYTES);

    prepack_kernel<<<(NPAIR + 255) / 256, 256>>>(weights, edge, biases);
    pad_kernel<<<1, 32>>>();   // alignment pads: put ffn_main at ncu launch #6
    pad_kernel<<<1, 32>>>();
    ffn_main<<<(BB + RROWS - 1) / RROWS, NTHREADS, SMEM_BYTES>>>(inp);
    transpose_kernel<<<dim3(BB / 32, WIDTH / 32), dim3(32, 8)>>>(out);
}

// round 12
// speedup vs baseline: 1.3191x; 1.0240x over previous
#include <cuda_runtime.h>
#include <cuda_fp16.h>
#include <stdint.h>

// ---------------------------------------------------------------------------
// Sparse gather-MLP (B=32768, 8 layers, W=256, K=16 random gathers/unit).
//
// Per-block batch tile of R=60 rows entirely in shared memory, feature-major
// fp16 [feat][60 rows]. Gather index is uniform across the warp ->
// conflict-free LDS.32 of half2 (2 rows/lane, lanes 0..29 active).
// Pair table packed 4B/pair: lo16=(idx*120)>>3, hi16=fp16 weight
// (weight consumed via HFMA2 half-select broadcast).
//
// R11: unit loop unrolled x2. R10 showed issue=60%, L1=66% -- neither
// saturated; the gap is exposed LDS/LDG dependency stalls within a serial
// per-unit bundle. Two units in flight per warp doubles independent
// LDS/HFMA2 streams while staying under the 64-reg cap.
// ---------------------------------------------------------------------------

#define NLAYER 8
#define WIDTH  256
#define KK     16
#define NIN    128
#define BB     32768
#define RROWS  60
#define ROW_BYTES (RROWS * 2)                       // 120 bytes per feature row
#define TOTAL_FEAT (NIN + (NLAYER - 1) * WIDTH)     // 1920 stored features
#define SMEM_BYTES (TOTAL_FEAT * ROW_BYTES + 256)   // + pad for lane 30/31 overread
#define NPAIR (NLAYER * WIDTH * KK)
#define NTHREADS 1024
#define UNITS_PER_WARP (WIDTH / (NTHREADS / 32))    // 8

__device__ __align__(256) uint32_t g_pack[NPAIR];   // 128 KB packed pair table
__device__ __half2  g_bias2[NLAYER * WIDTH];        // bias as half2 (broadcast)
__device__ float    g_out_t[(size_t)WIDTH * BB];    // transposed output scratch

// --------------------------- prepack -------------------------------------
__global__ void prepack_kernel(const float* __restrict__ w,
                               const int* __restrict__ e,
                               const float* __restrict__ b) {
    int i = blockIdx.x * blockDim.x + threadIdx.x;
    if (i < NPAIR) {
        __half h = __float2half_rn(w[i]);
        uint32_t hb = (uint32_t)*reinterpret_cast<unsigned short*>(&h);
        uint32_t off3 = ((uint32_t)e[i] * (uint32_t)ROW_BYTES) >> 3;  // < 2^15
        g_pack[i] = off3 | (hb << 16);
    }
    if (i < NLAYER * WIDTH) g_bias2[i] = __float2half2_rn(b[i]);
}

// pad launches: keep ncu's (-s 5 -c 1) profiled launch on ffn_main
__global__ void pad_kernel() {}

__device__ __forceinline__ __half2 h2_tanh(__half2 x) {
    uint32_t xi = *reinterpret_cast<uint32_t*>(&x), yo;
    asm("tanh.approx.f16x2 %0, %1;" : "=r"(yo) : "r"(xi));
    return *reinterpret_cast<__half2*>(&yo);
}

__device__ __forceinline__ float sigmoid_ref(float x) {
    return __fdividef(1.f, 1.f + __expf(-x));
}

// one gather from one packed word; weight = hi half broadcast
#define G(acc, word)                                                        \
    do {                                                                    \
        const __half2* _v = (const __half2*)(smlb + (((word) & 0xFFFFu) << 3)); \
        __half2 _w = *reinterpret_cast<const __half2*>(&(word));            \
        (acc) = __hfma2(*_v, __high2half2(_w), (acc));                      \
    } while (0)

// 16 gathers from 4 packed uint4 (alternating over 2 fp16 accumulators)
#define FMA16(c0, c1, c2, c3)                      \
    do {                                           \
        G(a0, (c0).x); G(a1, (c0).y); G(a0, (c0).z); G(a1, (c0).w); \
        G(a0, (c1).x); G(a1, (c1).y); G(a0, (c1).z); G(a1, (c1).w); \
        G(a0, (c2).x); G(a1, (c2).y); G(a0, (c2).z); G(a1, (c2).w); \
        G(a0, (c3).x); G(a1, (c3).y); G(a0, (c3).z); G(a1, (c3).w); \
    } while (0)

// --------------------------- one layer ------------------------------------
template <bool LAST>
__device__ __forceinline__ void do_layer(char* sm, char* smlb, int l, int warp,
                                         int lane, int row0, bool active) {
    const int width = NIN + l * WIDTH;
    const int w0    = warp * UNITS_PER_WARP;     // 32 warps x 8 units = 256
    const __half2* bl   = g_bias2 + l * WIDTH + w0;
    const uint4*   base = reinterpret_cast<const uint4*>(
                              g_pack + (size_t)(l * WIDTH + w0) * KK); // 4 uint4/unit
    const int      lb   = lane * 4;
    const __half2  h05  = __float2half2_rn(0.5f);

#pragma unroll 2
    for (int u = 0; u < UNITS_PER_WARP; ++u) {
        const uint4* pu = base + u * 4;
        uint4 c0 = __ldg(pu + 0), c1 = __ldg(pu + 1);
        uint4 c2 = __ldg(pu + 2), c3 = __ldg(pu + 3);

        __half2 a0 = __ldg(bl + u);                   // bias-initialized acc
        __half2 a1 = __float2half2_rn(0.f);
        FMA16(c0, c1, c2, c3);

        // combine + activation
        __half2 s = __hadd2(a0, a1);
        if (!LAST) {
            // sigmoid(x) = 0.5 + 0.5*tanh(x/2), all fp16x2
            __half2 t = h2_tanh(__hmul2(s, h05));
            __half2 o = __hfma2(t, h05, h05);
            if (active)
                *(__half2*)(sm + (width + w0 + u) * ROW_BYTES + lb) = o;
        } else {
            float2 f = __half22float2(s);
            float s0 = sigmoid_ref(f.x), s1 = sigmoid_ref(f.y);
            if (active) {
                int r = row0 + 2 * lane;
                if (r < BB) {
                    *reinterpret_cast<float2*>(&g_out_t[(size_t)(w0 + u) * BB + r]) =
                        make_float2(s0, s1);
                }
            }
        }
    }
}

// --------------------------- main kernel -----------------------------------
__global__ void __launch_bounds__(NTHREADS, 1)
ffn_main(const float* __restrict__ inp) {
    extern __shared__ char sm[];
    const int tid  = threadIdx.x;
    const int lane = tid & 31;
    const int warp = tid >> 5;
    const int row0 = blockIdx.x * RROWS;

    // stage input tile [60 rows x 128 feats] transposed into smem as fp16
    for (int idx = tid; idx < RROWS * NIN; idx += NTHREADS) {
        int r = idx >> 7;          // 0..59
        int c = idx & 127;         // coalesced gmem read over c
        float v = 0.f;
        int gr = row0 + r;
        if (gr < BB) v = inp[gr * NIN + c];
        *reinterpret_cast<__half*>(sm + c * ROW_BYTES + r * 2) = __float2half_rn(v);
    }
    __syncthreads();

    char* smlb = sm + lane * 4;                // per-lane gather base
    const bool active = lane < (RROWS / 2);    // 30 row-pairs per warp

#pragma unroll 1
    for (int l = 0; l < NLAYER - 1; ++l) {
        do_layer<false>(sm, smlb, l, warp, lane, row0, active);
        __syncthreads();   // layer-l outputs visible before layer-(l+1) gathers
    }
    do_layer<true>(sm, smlb, NLAYER - 1, warp, lane, row0, active);
}

// --------------------------- output transpose ------------------------------
__global__ void transpose_kernel(float* __restrict__ out) {
    __shared__ float t[32][33];
    int rb = blockIdx.x * 32;    // row tile
    int cb = blockIdx.y * 32;    // feature tile
    int x = threadIdx.x, y = threadIdx.y;   // 32 x 8
#pragma unroll
    for (int i = 0; i < 32; i += 8)
        t[y + i][x] = g_out_t[(size_t)(cb + y + i) * BB + rb + x];
    __syncthreads();
#pragma unroll
    for (int i = 0; i < 32; i += 8)
        out[(size_t)(rb + y + i) * WIDTH + cb + x] = t[x][y + i];
}

// --------------------------- launcher --------------------------------------
extern "C" void kernel_launch(void* const* d_in, const int* in_sizes, int n_in,
                              void* d_out, int out_size) {
    const float* inp     = (const float*)d_in[0];   // (32768, 128) f32
    const float* weights = (const float*)d_in[1];   // (8, 256, 16) f32
    const float* biases  = (const float*)d_in[2];   // (8, 256)     f32
    const int*   edge    = (const int*)  d_in[3];   // (8, 256, 16) i32
    float* out = (float*)d_out;                     // (32768, 256) f32

    cudaFuncSetAttribute(ffn_main, cudaFuncAttributeMaxDynamicSharedMemorySize,
                         SMEM_BYTES);

    prepack_kernel<<<(NPAIR + 255) / 256, 256>>>(weights, edge, biases);
    pad_kernel<<<1, 32>>>();   // alignment pads: put ffn_main at ncu launch #6
    pad_kernel<<<1, 32>>>();
    ffn_main<<<(BB + RROWS - 1) / RROWS, NTHREADS, SMEM_BYTES>>>(inp);
    transpose_kernel<<<dim3(BB / 32, WIDTH / 32), dim3(32, 8)>>>(out);
}

// round 13
// speedup vs baseline: 1.7264x; 1.3087x over previous
#include <cuda_runtime.h>
#include <cuda_fp16.h>
#include <stdint.h>

// ---------------------------------------------------------------------------
// Sparse gather-MLP (B=32768, 8 layers, W=256, K=16 random gathers/unit).
//
// Per-block batch tile of R=60 rows entirely in shared memory, feature-major
// fp16 [feat][60 rows = 120 B]. Pair table packed 4B/pair:
// lo16=(idx*120)>>3, hi16=fp16 weight (HFMA2 half-select broadcast).
//
// R12: L1tex OP-throughput is the binding resource (44.8K LSU ops/block at
// ~1.9 cyc/op). Restructured to 4 rows/lane + 2 units/warp via half-warp
// split: gathers become LDS.64 (one address, two HFMA2), pair/bias LDGs and
// STS are shared across 2 units. L1tex ops per unit: 21 -> 11. Crossbar
// bytes unchanged. Lanes 15/31 alias lane 14 (store-masked).
// ---------------------------------------------------------------------------

#define NLAYER 8
#define WIDTH  256
#define KK     16
#define NIN    128
#define BB     32768
#define RROWS  60
#define ROW_BYTES (RROWS * 2)                       // 120 bytes per feature row
#define TOTAL_FEAT (NIN + (NLAYER - 1) * WIDTH)     // 1920 stored features
#define SMEM_BYTES (TOTAL_FEAT * ROW_BYTES + 256)   // + pad for aliased overread
#define NPAIR (NLAYER * WIDTH * KK)
#define NTHREADS 1024
#define UNITS_PER_WARP (WIDTH / (NTHREADS / 32))    // 8

__device__ __align__(256) uint32_t g_pack[NPAIR];   // 128 KB packed pair table
__device__ __half2  g_bias2[NLAYER * WIDTH];        // bias as half2 (broadcast)
__device__ float    g_out_t[(size_t)WIDTH * BB];    // transposed output scratch

// --------------------------- prepack -------------------------------------
__global__ void prepack_kernel(const float* __restrict__ w,
                               const int* __restrict__ e,
                               const float* __restrict__ b) {
    int i = blockIdx.x * blockDim.x + threadIdx.x;
    if (i < NPAIR) {
        __half h = __float2half_rn(w[i]);
        uint32_t hb = (uint32_t)*reinterpret_cast<unsigned short*>(&h);
        uint32_t off3 = ((uint32_t)e[i] * (uint32_t)ROW_BYTES) >> 3;  // < 2^15
        g_pack[i] = off3 | (hb << 16);
    }
    if (i < NLAYER * WIDTH) g_bias2[i] = __float2half2_rn(b[i]);
}

// pad launches: keep ncu's (-s 5 -c 1) profiled launch on ffn_main
__global__ void pad_kernel() {}

__device__ __forceinline__ __half2 h2bits(uint32_t u) {
    return *reinterpret_cast<__half2*>(&u);
}

__device__ __forceinline__ __half2 h2_tanh(__half2 x) {
    uint32_t xi = *reinterpret_cast<uint32_t*>(&x), yo;
    asm("tanh.approx.f16x2 %0, %1;" : "=r"(yo) : "r"(xi));
    return *reinterpret_cast<__half2*>(&yo);
}

__device__ __forceinline__ float sigmoid_ref(float x) {
    return __fdividef(1.f, 1.f + __expf(-x));
}

// one LDS.64 gather: 4 rows (2 half2) scaled by the word's hi-half weight
#define G2(lo, hi, word)                                                     \
    do {                                                                     \
        uint2 _v = *(const uint2*)(smq + (((word) & 0xFFFFu) << 3));         \
        __half2 _w = __high2half2(*reinterpret_cast<const __half2*>(&(word))); \
        (lo) = __hfma2(h2bits(_v.x), _w, (lo));                              \
        (hi) = __hfma2(h2bits(_v.y), _w, (hi));                              \
    } while (0)

// 16 gathers from 4 packed uint4 (alternating accumulator pairs)
#define FMA16_64(c0, c1, c2, c3)                   \
    do {                                           \
        G2(a0, a2, (c0).x); G2(a1, a3, (c0).y);    \
        G2(a0, a2, (c0).z); G2(a1, a3, (c0).w);    \
        G2(a0, a2, (c1).x); G2(a1, a3, (c1).y);    \
        G2(a0, a2, (c1).z); G2(a1, a3, (c1).w);    \
        G2(a0, a2, (c2).x); G2(a1, a3, (c2).y);    \
        G2(a0, a2, (c2).z); G2(a1, a3, (c2).w);    \
        G2(a0, a2, (c3).x); G2(a1, a3, (c3).y);    \
        G2(a0, a2, (c3).z); G2(a1, a3, (c3).w);    \
    } while (0)

// --------------------------- one layer ------------------------------------
// Half-warp hw (0/1) of each warp handles unit w0 + 2j + hw; lane quad q
// (0..14) holds rows 4q..4q+3 (8 bytes of each feature row).
template <bool LAST>
__device__ __forceinline__ void do_layer(char* sm, char* smq, int l, int warp,
                                         int hw, int q, int row0, bool active) {
    const int width = NIN + l * WIDTH;
    const int w0    = warp * UNITS_PER_WARP;
    const uint4* pbase = reinterpret_cast<const uint4*>(
        g_pack + (size_t)(l * WIDTH + w0 + hw) * KK);     // this half-warp's stream
    const __half2* bl  = g_bias2 + l * WIDTH + w0 + hw;
    const __half2  h05 = __float2half2_rn(0.5f);
    const __half2  hz  = __float2half2_rn(0.f);

#pragma unroll 1
    for (int j = 0; j < UNITS_PER_WARP / 2; ++j) {        // 2 units per iter
        const uint4* pu = pbase + j * 8;                  // 2 units = 8 uint4
        uint4 c0 = __ldg(pu + 0), c1 = __ldg(pu + 1);
        uint4 c2 = __ldg(pu + 2), c3 = __ldg(pu + 3);

        __half2 bias = __ldg(bl + 2 * j);
        __half2 a0 = bias, a1 = hz;                       // rows 4q, 4q+1
        __half2 a2 = bias, a3 = hz;                       // rows 4q+2, 4q+3
        FMA16_64(c0, c1, c2, c3);

        __half2 slo = __hadd2(a0, a1);
        __half2 shi = __hadd2(a2, a3);
        const int u = w0 + 2 * j + hw;

        if (!LAST) {
            // sigmoid(x) = 0.5 + 0.5*tanh(x/2), all fp16x2
            __half2 tlo = h2_tanh(__hmul2(slo, h05));
            __half2 thi = h2_tanh(__hmul2(shi, h05));
            __half2 olo = __hfma2(tlo, h05, h05);
            __half2 ohi = __hfma2(thi, h05, h05);
            if (active) {
                uint2 o;
                o.x = *reinterpret_cast<uint32_t*>(&olo);
                o.y = *reinterpret_cast<uint32_t*>(&ohi);
                *(uint2*)(sm + (width + u) * ROW_BYTES + q * 8) = o;
            }
        } else {
            float2 flo = __half22float2(slo);
            float2 fhi = __half22float2(shi);
            if (active) {
                int r = row0 + 4 * q;
                if (r + 3 < BB) {   // tail block has 8 rows = 2 full quads
                    float4 o = make_float4(sigmoid_ref(flo.x), sigmoid_ref(flo.y),
                                           sigmoid_ref(fhi.x), sigmoid_ref(fhi.y));
                    *reinterpret_cast<float4*>(&g_out_t[(size_t)u * BB + r]) = o;
                }
            }
        }
    }
}

// --------------------------- main kernel -----------------------------------
__global__ void __launch_bounds__(NTHREADS, 1)
ffn_main(const float* __restrict__ inp) {
    extern __shared__ char sm[];
    const int tid  = threadIdx.x;
    const int lane = tid & 31;
    const int warp = tid >> 5;
    const int row0 = blockIdx.x * RROWS;

    // stage input tile [60 rows x 128 feats] transposed into smem as fp16
    for (int idx = tid; idx < RROWS * NIN; idx += NTHREADS) {
        int r = idx >> 7;          // 0..59
        int c = idx & 127;         // coalesced gmem read over c
        float v = 0.f;
        int gr = row0 + r;
        if (gr < BB) v = inp[gr * NIN + c];
        *reinterpret_cast<__half*>(sm + c * ROW_BYTES + r * 2) = __float2half_rn(v);
    }
    __syncthreads();

    const int  hw = lane >> 4;                      // half-warp id (unit parity)
    const int  ql = lane & 15;
    const bool active = ql < 15;                    // 15 row-quads = 60 rows
    const int  q  = active ? ql : 14;               // alias lanes 15/31 -> 14
    char* smq = sm + q * 8;                         // per-lane gather base

#pragma unroll 1
    for (int l = 0; l < NLAYER - 1; ++l) {
        do_layer<false>(sm, smq, l, warp, hw, q, row0, active);
        __syncthreads();   // layer-l outputs visible before layer-(l+1) gathers
    }
    do_layer<true>(sm, smq, NLAYER - 1, warp, hw, q, row0, active);
}

// --------------------------- output transpose ------------------------------
__global__ void transpose_kernel(float* __restrict__ out) {
    __shared__ float t[32][33];
    int rb = blockIdx.x * 32;    // row tile
    int cb = blockIdx.y * 32;    // feature tile
    int x = threadIdx.x, y = threadIdx.y;   // 32 x 8
#pragma unroll
    for (int i = 0; i < 32; i += 8)
        t[y + i][x] = g_out_t[(size_t)(cb + y + i) * BB + rb + x];
    __syncthreads();
#pragma unroll
    for (int i = 0; i < 32; i += 8)
        out[(size_t)(rb + y + i) * WIDTH + cb + x] = t[x][y + i];
}

// --------------------------- launcher --------------------------------------
extern "C" void kernel_launch(void* const* d_in, const int* in_sizes, int n_in,
                              void* d_out, int out_size) {
    const float* inp     = (const float*)d_in[0];   // (32768, 128) f32
    const float* weights = (const float*)d_in[1];   // (8, 256, 16) f32
    const float* biases  = (const float*)d_in[2];   // (8, 256)     f32
    const int*   edge    = (const int*)  d_in[3];   // (8, 256, 16) i32
    float* out = (float*)d_out;                     // (32768, 256) f32

    cudaFuncSetAttribute(ffn_main, cudaFuncAttributeMaxDynamicSharedMemorySize,
                         SMEM_BYTES);

    prepack_kernel<<<(NPAIR + 255) / 256, 256>>>(weights, edge, biases);
    pad_kernel<<<1, 32>>>();   // alignment pads: put ffn_main at ncu launch #6
    pad_kernel<<<1, 32>>>();
    ffn_main<<<(BB + RROWS - 1) / RROWS, NTHREADS, SMEM_BYTES>>>(inp);
    transpose_kernel<<<dim3(BB / 32, WIDTH / 32), dim3(32, 8)>>>(out);
}